// round 12
// baseline (speedup 1.0000x reference)
#include <cuda_runtime.h>
#include <cuda_bf16.h>
#include <mma.h>
#include <cstdint>

using namespace nvcuda;

#define BATCH 256
#define SEQ   512
#define NIN   512
#define NH    128
#define G4    512   // 4*NH
#define MTOT  (BATCH * SEQ)

// -------- scratch (static device globals; no runtime allocation) --------
__device__ float g_xg[(size_t)SEQ * BATCH * G4];   // x_gates[s][b][col]
__device__ float g_hlast[BATCH * NH];

// ---------------- helpers ----------------
__device__ __forceinline__ uint64_t ffma2(uint64_t a, uint64_t b, uint64_t c) {
    uint64_t d;
    asm("fma.rn.f32x2 %0, %1, %2, %3;" : "=l"(d) : "l"(a), "l"(b), "l"(c));
    return d;
}
__device__ __forceinline__ uint64_t pack2(float lo, float hi) {
    uint64_t d; asm("mov.b64 %0, {%1, %2};" : "=l"(d) : "f"(lo), "f"(hi)); return d;
}
__device__ __forceinline__ void unpack2(uint64_t v, float& lo, float& hi) {
    asm("mov.b64 {%0, %1}, %2;" : "=f"(lo), "=f"(hi) : "l"(v));
}
__device__ __forceinline__ void cluster_sync_inline() {
    asm volatile("barrier.cluster.arrive.aligned;" ::: "memory");
    asm volatile("barrier.cluster.wait.aligned;" ::: "memory");
}
__device__ __forceinline__ float tanh_a(float x) {
    float r; asm("tanh.approx.f32 %0, %1;" : "=f"(r) : "f"(x)); return r;
}
__device__ __forceinline__ float sigmoid_a(float x) {
    return fmaf(tanh_a(0.5f * x), 0.5f, 0.5f);
}
__device__ __forceinline__ void cp_async16(void* smem, const void* g) {
    uint32_t s = (uint32_t)__cvta_generic_to_shared(smem);
    asm volatile("cp.async.cg.shared.global [%0], [%1], 16;" :: "r"(s), "l"(g));
}
__device__ __forceinline__ void mbar_init(uint32_t addr, uint32_t cnt) {
    asm volatile("mbarrier.init.shared.b64 [%0], %1;" :: "r"(addr), "r"(cnt) : "memory");
}
__device__ __forceinline__ void mbar_arrive_remote(uint32_t raddr) {
    asm volatile("mbarrier.arrive.release.cluster.shared::cluster.b64 _, [%0];"
                 :: "r"(raddr) : "memory");
}
__device__ __forceinline__ void mbar_wait_cluster(uint32_t addr, uint32_t parity) {
    uint32_t done;
    do {
        asm volatile(
            "{\n\t.reg .pred p;\n\t"
            "mbarrier.try_wait.parity.acquire.cluster.shared::cta.b64 p, [%1], %2, 0x989680;\n\t"
            "selp.b32 %0, 1, 0, p;\n\t}"
            : "=r"(done) : "r"(addr), "r"(parity) : "memory");
    } while (!done);
}

// ================= Phase 1: x_gates = x @ Wi (tf32 wmma, fragment-pipelined) =================
// Fragment double-buffer: kk+1's LDSM issue during kk's HMMA -> tensor pipe stays fed
// (fixes the LDSM/HMMA phase convoy that capped tensor at ~53%).
#define BM 128
#define BN 128
#define BK 32
#define LDA 40    // 32 + 8 pad (floats)
#define LDB 136   // 128 + 8 pad
#define SMEM_G ((2 * BM * LDA + 2 * BK * LDB) * 4)   // 75776 bytes

__global__ void __launch_bounds__(256) gemm_xw(const float* __restrict__ X,
                                               const float* __restrict__ Wi)
{
    extern __shared__ float dsm[];
    float (*As)[BM][LDA] = (float (*)[BM][LDA])dsm;
    float (*Bs)[BK][LDB] = (float (*)[BK][LDB])(dsm + 2 * BM * LDA);

    const int m0 = blockIdx.x * BM;
    const int n0 = blockIdx.y * BN;
    const int tid = threadIdx.x;
    const int warp = tid >> 5;
    const int wm = warp >> 2;     // 0..1 : 64-row slab
    const int wn = warp & 3;      // 0..3 : 32-col slab

    typedef wmma::fragment<wmma::matrix_a, 16, 16, 8, wmma::precision::tf32, wmma::row_major> FragA;
    typedef wmma::fragment<wmma::matrix_b, 16, 16, 8, wmma::precision::tf32, wmma::row_major> FragB;

    wmma::fragment<wmma::accumulator, 16, 16, 8, float> c[4][2];
    #pragma unroll
    for (int i = 0; i < 4; i++)
        #pragma unroll
        for (int j = 0; j < 2; j++)
            wmma::fill_fragment(c[i][j], 0.0f);

    auto load_tiles = [&](int kt, int buf) {
        const int k0 = kt * BK;
        #pragma unroll
        for (int q = 0; q < 4; q++) {
            int e = tid + q * 256;           // 0..1023
            int row = e >> 3;                // 0..127
            int c4 = (e & 7) * 4;            // 0..28
            cp_async16(&As[buf][row][c4], &X[(size_t)(m0 + row) * NIN + k0 + c4]);
        }
        #pragma unroll
        for (int q = 0; q < 4; q++) {
            int e = tid + q * 256;
            int row = e >> 5;                // 0..31
            int c4 = (e & 31) * 4;           // 0..124
            cp_async16(&Bs[buf][row][c4], &Wi[(size_t)(k0 + row) * G4 + n0 + c4]);
        }
        asm volatile("cp.async.commit_group;" ::: "memory");
    };

    load_tiles(0, 0);

    FragA af[2][4];
    FragB bf[2][2];

    auto load_frags = [&](int buf, int kk, int set) {
        #pragma unroll
        for (int i = 0; i < 4; i++)
            wmma::load_matrix_sync(af[set][i], &As[buf][wm * 64 + i * 16][kk], LDA);
        #pragma unroll
        for (int j = 0; j < 2; j++)
            wmma::load_matrix_sync(bf[set][j], &Bs[buf][kk][wn * 32 + j * 16], LDB);
    };
    auto do_mmas = [&](int set) {
        #pragma unroll
        for (int i = 0; i < 4; i++)
            #pragma unroll
            for (int j = 0; j < 2; j++)
                wmma::mma_sync(c[i][j], af[set][i], bf[set][j], c[i][j]);
    };

    const int NT = NIN / BK;   // 16
    for (int kt = 0; kt < NT; kt++) {
        if (kt + 1 < NT) {
            load_tiles(kt + 1, (kt + 1) & 1);
            asm volatile("cp.async.wait_group 1;" ::: "memory");
        } else {
            asm volatile("cp.async.wait_group 0;" ::: "memory");
        }
        __syncthreads();

        const int buf = kt & 1;
        // Software pipeline over kk = 0,8,16,24: LDSM(next) overlaps HMMA(curr)
        load_frags(buf, 0, 0);
        #pragma unroll
        for (int kk = 0; kk < BK; kk += 8) {
            const int cur = (kk >> 3) & 1;
            if (kk + 8 < BK) load_frags(buf, kk + 8, cur ^ 1);
            do_mmas(cur);
        }
        __syncthreads();
    }

    // Epilogue: gmem row m = b*SEQ + s -> g_xg row s*BATCH + b. 16-row tiles: constant b.
    #pragma unroll
    for (int i = 0; i < 4; i++) {
        int m = m0 + wm * 64 + i * 16;
        int b = m >> 9;
        int s = m & 511;
        float* base = g_xg + ((size_t)s * BATCH + b) * G4 + n0 + wn * 32;
        #pragma unroll
        for (int j = 0; j < 2; j++)
            wmma::store_matrix_sync(base + j * 16, c[i][j], (size_t)BATCH * G4, wmma::mem_row_major);
    }
}

// ================= Phase 2: LSTM recurrence (R6-proven, frozen) =================
__global__ void __launch_bounds__(512, 1) __cluster_dims__(2, 1, 1)
lstm_rec(const float* __restrict__ Wh, const float* __restrict__ bias)
{
    __shared__ __align__(16) float h_s[2][4][NH];     // double-buffered h
    __shared__ float part[2][4][4][64];               // [kh][gate][b][jloc]
    __shared__ __align__(8) unsigned long long mbar;

    const int tid  = threadIdx.x;
    const int lane = tid & 31;
    const int warp = tid >> 5;
    const int rank  = blockIdx.x & 1;
    const int bbase = (blockIdx.x >> 1) * 4;

    const int kh   = warp >> 3;
    const int w7   = warp & 7;
    const int gate = w7 >> 1;
    const int jloc = (w7 & 1) * 32 + lane;
    const int colg = gate * NH + rank * 64 + jloc;

    uint64_t w[32];
    #pragma unroll
    for (int i = 0; i < 32; i++) {
        int k = kh * 64 + 2 * i;
        w[i] = pack2(Wh[(size_t)k * G4 + colg], Wh[(size_t)(k + 1) * G4 + colg]);
    }

    const int ub = tid >> 6;
    const int uj = tid & 63;
    const int hidx = rank * 64 + uj;
    float bi = 0.f, bfo = 0.f, bg = 0.f, bo = 0.f;
    if (tid < 256) {
        bi  = bias[0 * NH + hidx];
        bfo = bias[1 * NH + hidx];
        bg  = bias[2 * NH + hidx];
        bo  = bias[3 * NH + hidx];
    }
    float c_reg = 0.0f;

    const uint32_t mloc = (uint32_t)__cvta_generic_to_shared(&mbar);
    uint32_t mrem;
    asm("mapa.shared::cluster.u32 %0, %1, %2;" : "=r"(mrem) : "r"(mloc), "r"(rank ^ 1));
    uint32_t hrem[2];
    #pragma unroll
    for (int pp = 0; pp < 2; pp++) {
        uint32_t la = (uint32_t)__cvta_generic_to_shared(&h_s[pp][ub][hidx]);
        asm("mapa.shared::cluster.u32 %0, %1, %2;" : "=r"(hrem[pp]) : "r"(la), "r"(rank ^ 1));
    }

    if (tid == 0) mbar_init(mloc, 1);
    for (int i = tid; i < 4 * NH; i += 512) (&h_s[0][0][0])[i] = 0.0f;
    __syncthreads();
    cluster_sync_inline();              // peer mbar init'd + h zeroed before any traffic
    if (tid == 0) mbar_arrive_remote(mrem);   // phase 0: peer "step -1 output ready"

    int p = 0;
    for (int s = 0; s < SEQ; s++) {
        float xgi = 0.f, xgf = 0.f, xgg = 0.f, xgo = 0.f;
        if (tid < 256) {
            const float* xp = g_xg + ((size_t)s * BATCH + bbase + ub) * G4 + hidx;
            xgi = xp[0];
            xgf = xp[NH];
            xgg = xp[2 * NH];
            xgo = xp[3 * NH];
        }

        #define DO_DOT()                                                          \
        do {                                                                      \
            _Pragma("unroll")                                                     \
            for (int b = 0; b < 4; b++) {                                         \
                const ulonglong2* h2 = (const ulonglong2*)&h_s[p][b][kh * 64];    \
                uint64_t a0 = 0ull, a1 = 0ull;                                    \
                _Pragma("unroll")                                                 \
                for (int i = 0; i < 8; i++) {                                     \
                    ulonglong2 ha = h2[2 * i];                                    \
                    ulonglong2 hb = h2[2 * i + 1];                                \
                    a0 = ffma2(ha.x, w[4 * i + 0], a0);                           \
                    a0 = ffma2(ha.y, w[4 * i + 1], a0);                           \
                    a1 = ffma2(hb.x, w[4 * i + 2], a1);                           \
                    a1 = ffma2(hb.y, w[4 * i + 3], a1);                           \
                }                                                                 \
                float l0, h0, l1, h1;                                             \
                unpack2(a0, l0, h0);                                              \
                unpack2(a1, l1, h1);                                              \
                part[kh][gate][b][jloc] = (l0 + h0) + (l1 + h1);                  \
            }                                                                     \
        } while (0)

        if (kh == rank) {
            DO_DOT();                               // local half: no peer dependency
            mbar_wait_cluster(mloc, s & 1);         // then align with peer phase
        } else {
            mbar_wait_cluster(mloc, s & 1);         // peer h for step s
            DO_DOT();
        }
        __syncthreads();                            // partials visible

        if (tid < 256) {
            float gi = part[0][0][ub][uj] + part[1][0][ub][uj] + xgi + bi;
            float gf = part[0][1][ub][uj] + part[1][1][ub][uj] + xgf + bfo;
            float gg = part[0][2][ub][uj] + part[1][2][ub][uj] + xgg + bg;
            float go = part[0][3][ub][uj] + part[1][3][ub][uj] + xgo + bo;
            c_reg = sigmoid_a(gf) * c_reg + sigmoid_a(gi) * tanh_a(gg);
            float hv = sigmoid_a(go) * tanh_a(c_reg);
            h_s[p ^ 1][ub][hidx] = hv;
            asm volatile("st.shared::cluster.f32 [%0], %1;"
                         :: "r"(hrem[p ^ 1]), "f"(hv) : "memory");
            if (s == SEQ - 1) g_hlast[(bbase + ub) * NH + hidx] = hv;
        }
        __syncthreads();                            // drains STS (incl. DSMEM) before arrive
        if (tid == 0) mbar_arrive_remote(mrem);     // single release-arrive
        p ^= 1;
    }
    cluster_sync_inline();   // keep both CTAs alive for in-flight DSMEM traffic
}

// ================= Phase 3: logits = h_last @ Wd + bd =================
__global__ void final_dense(const float* __restrict__ Wd, const float* __restrict__ bd,
                            float* __restrict__ out)
{
    int b = threadIdx.x;   // 256 threads, 1 block
    float a0 = bd[0], a1 = bd[1];
    const float* hp = g_hlast + b * NH;
    #pragma unroll 8
    for (int k = 0; k < NH; k++) {
        float h = hp[k];
        a0 += h * Wd[k * 2 + 0];
        a1 += h * Wd[k * 2 + 1];
    }
    out[b * 2 + 0] = a0;
    out[b * 2 + 1] = a1;
}

// ================= launch =================
extern "C" void kernel_launch(void* const* d_in, const int* in_sizes, int n_in,
                              void* d_out, int out_size)
{
    const float* x  = (const float*)d_in[0];
    const float* Wi = (const float*)d_in[1];
    const float* Wh = (const float*)d_in[2];
    const float* b  = (const float*)d_in[3];
    const float* Wd = (const float*)d_in[4];
    const float* bd = (const float*)d_in[5];
    float* out = (float*)d_out;

    cudaFuncSetAttribute(gemm_xw, cudaFuncAttributeMaxDynamicSharedMemorySize, SMEM_G);

    dim3 g1((BATCH * SEQ) / BM, G4 / BN);   // 1024 x 4
    gemm_xw<<<g1, 256, SMEM_G>>>(x, Wi);
    lstm_rec<<<128, 512>>>(Wh, b);          // 64 clusters of 2 CTAs
    final_dense<<<1, 256>>>(Wd, bd, out);
}

// round 13
// speedup vs baseline: 1.0020x; 1.0020x over previous
#include <cuda_runtime.h>
#include <cuda_bf16.h>
#include <mma.h>
#include <cstdint>

using namespace nvcuda;

#define BATCH 256
#define SEQ   512
#define NIN   512
#define NH    128
#define G4    512   // 4*NH
#define MTOT  (BATCH * SEQ)

// -------- scratch (static device globals; no runtime allocation) --------
__device__ float g_xg[(size_t)SEQ * BATCH * G4];   // x_gates[s][b][col]
__device__ float g_hlast[BATCH * NH];

// ---------------- helpers ----------------
__device__ __forceinline__ uint64_t ffma2(uint64_t a, uint64_t b, uint64_t c) {
    uint64_t d;
    asm("fma.rn.f32x2 %0, %1, %2, %3;" : "=l"(d) : "l"(a), "l"(b), "l"(c));
    return d;
}
__device__ __forceinline__ uint64_t pack2(float lo, float hi) {
    uint64_t d; asm("mov.b64 %0, {%1, %2};" : "=l"(d) : "f"(lo), "f"(hi)); return d;
}
__device__ __forceinline__ void unpack2(uint64_t v, float& lo, float& hi) {
    asm("mov.b64 {%0, %1}, %2;" : "=f"(lo), "=f"(hi) : "l"(v));
}
__device__ __forceinline__ void cluster_sync_inline() {
    asm volatile("barrier.cluster.arrive.aligned;" ::: "memory");
    asm volatile("barrier.cluster.wait.aligned;" ::: "memory");
}
__device__ __forceinline__ float tanh_a(float x) {
    float r; asm("tanh.approx.f32 %0, %1;" : "=f"(r) : "f"(x)); return r;
}
__device__ __forceinline__ float sigmoid_a(float x) {
    return fmaf(tanh_a(0.5f * x), 0.5f, 0.5f);
}
__device__ __forceinline__ void cp_async16(void* smem, const void* g) {
    uint32_t s = (uint32_t)__cvta_generic_to_shared(smem);
    asm volatile("cp.async.cg.shared.global [%0], [%1], 16;" :: "r"(s), "l"(g));
}
__device__ __forceinline__ void mbar_init(uint32_t addr, uint32_t cnt) {
    asm volatile("mbarrier.init.shared.b64 [%0], %1;" :: "r"(addr), "r"(cnt) : "memory");
}
__device__ __forceinline__ void mbar_arrive_remote(uint32_t raddr) {
    asm volatile("mbarrier.arrive.release.cluster.shared::cluster.b64 _, [%0];"
                 :: "r"(raddr) : "memory");
}
__device__ __forceinline__ void mbar_wait_cluster(uint32_t addr, uint32_t parity) {
    uint32_t done;
    do {
        asm volatile(
            "{\n\t.reg .pred p;\n\t"
            "mbarrier.try_wait.parity.acquire.cluster.shared::cta.b64 p, [%1], %2, 0x989680;\n\t"
            "selp.b32 %0, 1, 0, p;\n\t}"
            : "=r"(done) : "r"(addr), "r"(parity) : "memory");
    } while (!done);
}

// ================= Phase 1: x_gates = x @ Wi (tf32 wmma, fragment-pipelined) =================
// Fragment double-buffer: kk+1's LDSM issue during kk's HMMA -> tensor pipe stays fed
// (fixes the LDSM/HMMA phase convoy that capped tensor at ~53%).
#define BM 128
#define BN 128
#define BK 32
#define LDA 40    // 32 + 8 pad (floats)
#define LDB 136   // 128 + 8 pad
#define SMEM_G ((2 * BM * LDA + 2 * BK * LDB) * 4)   // 75776 bytes

__global__ void __launch_bounds__(256) gemm_xw(const float* __restrict__ X,
                                               const float* __restrict__ Wi)
{
    extern __shared__ float dsm[];
    float (*As)[BM][LDA] = (float (*)[BM][LDA])dsm;
    float (*Bs)[BK][LDB] = (float (*)[BK][LDB])(dsm + 2 * BM * LDA);

    const int m0 = blockIdx.x * BM;
    const int n0 = blockIdx.y * BN;
    const int tid = threadIdx.x;
    const int warp = tid >> 5;
    const int wm = warp >> 2;     // 0..1 : 64-row slab
    const int wn = warp & 3;      // 0..3 : 32-col slab

    typedef wmma::fragment<wmma::matrix_a, 16, 16, 8, wmma::precision::tf32, wmma::row_major> FragA;
    typedef wmma::fragment<wmma::matrix_b, 16, 16, 8, wmma::precision::tf32, wmma::row_major> FragB;

    wmma::fragment<wmma::accumulator, 16, 16, 8, float> c[4][2];
    #pragma unroll
    for (int i = 0; i < 4; i++)
        #pragma unroll
        for (int j = 0; j < 2; j++)
            wmma::fill_fragment(c[i][j], 0.0f);

    auto load_tiles = [&](int kt, int buf) {
        const int k0 = kt * BK;
        #pragma unroll
        for (int q = 0; q < 4; q++) {
            int e = tid + q * 256;           // 0..1023
            int row = e >> 3;                // 0..127
            int c4 = (e & 7) * 4;            // 0..28
            cp_async16(&As[buf][row][c4], &X[(size_t)(m0 + row) * NIN + k0 + c4]);
        }
        #pragma unroll
        for (int q = 0; q < 4; q++) {
            int e = tid + q * 256;
            int row = e >> 5;                // 0..31
            int c4 = (e & 31) * 4;           // 0..124
            cp_async16(&Bs[buf][row][c4], &Wi[(size_t)(k0 + row) * G4 + n0 + c4]);
        }
        asm volatile("cp.async.commit_group;" ::: "memory");
    };

    load_tiles(0, 0);

    FragA af[2][4];
    FragB bf[2][2];

    auto load_frags = [&](int buf, int kk, int set) {
        #pragma unroll
        for (int i = 0; i < 4; i++)
            wmma::load_matrix_sync(af[set][i], &As[buf][wm * 64 + i * 16][kk], LDA);
        #pragma unroll
        for (int j = 0; j < 2; j++)
            wmma::load_matrix_sync(bf[set][j], &Bs[buf][kk][wn * 32 + j * 16], LDB);
    };
    auto do_mmas = [&](int set) {
        #pragma unroll
        for (int i = 0; i < 4; i++)
            #pragma unroll
            for (int j = 0; j < 2; j++)
                wmma::mma_sync(c[i][j], af[set][i], bf[set][j], c[i][j]);
    };

    const int NT = NIN / BK;   // 16
    for (int kt = 0; kt < NT; kt++) {
        if (kt + 1 < NT) {
            load_tiles(kt + 1, (kt + 1) & 1);
            asm volatile("cp.async.wait_group 1;" ::: "memory");
        } else {
            asm volatile("cp.async.wait_group 0;" ::: "memory");
        }
        __syncthreads();

        const int buf = kt & 1;
        // Software pipeline over kk = 0,8,16,24: LDSM(next) overlaps HMMA(curr)
        load_frags(buf, 0, 0);
        #pragma unroll
        for (int kk = 0; kk < BK; kk += 8) {
            const int cur = (kk >> 3) & 1;
            if (kk + 8 < BK) load_frags(buf, kk + 8, cur ^ 1);
            do_mmas(cur);
        }
        __syncthreads();
    }

    // Epilogue: gmem row m = b*SEQ + s -> g_xg row s*BATCH + b. 16-row tiles: constant b.
    #pragma unroll
    for (int i = 0; i < 4; i++) {
        int m = m0 + wm * 64 + i * 16;
        int b = m >> 9;
        int s = m & 511;
        float* base = g_xg + ((size_t)s * BATCH + b) * G4 + n0 + wn * 32;
        #pragma unroll
        for (int j = 0; j < 2; j++)
            wmma::store_matrix_sync(base + j * 16, c[i][j], (size_t)BATCH * G4, wmma::mem_row_major);
    }
}

// ================= Phase 2: LSTM recurrence (R6-proven, frozen) =================
__global__ void __launch_bounds__(512, 1) __cluster_dims__(2, 1, 1)
lstm_rec(const float* __restrict__ Wh, const float* __restrict__ bias)
{
    __shared__ __align__(16) float h_s[2][4][NH];     // double-buffered h
    __shared__ float part[2][4][4][64];               // [kh][gate][b][jloc]
    __shared__ __align__(8) unsigned long long mbar;

    const int tid  = threadIdx.x;
    const int lane = tid & 31;
    const int warp = tid >> 5;
    const int rank  = blockIdx.x & 1;
    const int bbase = (blockIdx.x >> 1) * 4;

    const int kh   = warp >> 3;
    const int w7   = warp & 7;
    const int gate = w7 >> 1;
    const int jloc = (w7 & 1) * 32 + lane;
    const int colg = gate * NH + rank * 64 + jloc;

    uint64_t w[32];
    #pragma unroll
    for (int i = 0; i < 32; i++) {
        int k = kh * 64 + 2 * i;
        w[i] = pack2(Wh[(size_t)k * G4 + colg], Wh[(size_t)(k + 1) * G4 + colg]);
    }

    const int ub = tid >> 6;
    const int uj = tid & 63;
    const int hidx = rank * 64 + uj;
    float bi = 0.f, bfo = 0.f, bg = 0.f, bo = 0.f;
    if (tid < 256) {
        bi  = bias[0 * NH + hidx];
        bfo = bias[1 * NH + hidx];
        bg  = bias[2 * NH + hidx];
        bo  = bias[3 * NH + hidx];
    }
    float c_reg = 0.0f;

    const uint32_t mloc = (uint32_t)__cvta_generic_to_shared(&mbar);
    uint32_t mrem;
    asm("mapa.shared::cluster.u32 %0, %1, %2;" : "=r"(mrem) : "r"(mloc), "r"(rank ^ 1));
    uint32_t hrem[2];
    #pragma unroll
    for (int pp = 0; pp < 2; pp++) {
        uint32_t la = (uint32_t)__cvta_generic_to_shared(&h_s[pp][ub][hidx]);
        asm("mapa.shared::cluster.u32 %0, %1, %2;" : "=r"(hrem[pp]) : "r"(la), "r"(rank ^ 1));
    }

    if (tid == 0) mbar_init(mloc, 1);
    for (int i = tid; i < 4 * NH; i += 512) (&h_s[0][0][0])[i] = 0.0f;
    __syncthreads();
    cluster_sync_inline();              // peer mbar init'd + h zeroed before any traffic
    if (tid == 0) mbar_arrive_remote(mrem);   // phase 0: peer "step -1 output ready"

    int p = 0;
    for (int s = 0; s < SEQ; s++) {
        float xgi = 0.f, xgf = 0.f, xgg = 0.f, xgo = 0.f;
        if (tid < 256) {
            const float* xp = g_xg + ((size_t)s * BATCH + bbase + ub) * G4 + hidx;
            xgi = xp[0];
            xgf = xp[NH];
            xgg = xp[2 * NH];
            xgo = xp[3 * NH];
        }

        #define DO_DOT()                                                          \
        do {                                                                      \
            _Pragma("unroll")                                                     \
            for (int b = 0; b < 4; b++) {                                         \
                const ulonglong2* h2 = (const ulonglong2*)&h_s[p][b][kh * 64];    \
                uint64_t a0 = 0ull, a1 = 0ull;                                    \
                _Pragma("unroll")                                                 \
                for (int i = 0; i < 8; i++) {                                     \
                    ulonglong2 ha = h2[2 * i];                                    \
                    ulonglong2 hb = h2[2 * i + 1];                                \
                    a0 = ffma2(ha.x, w[4 * i + 0], a0);                           \
                    a0 = ffma2(ha.y, w[4 * i + 1], a0);                           \
                    a1 = ffma2(hb.x, w[4 * i + 2], a1);                           \
                    a1 = ffma2(hb.y, w[4 * i + 3], a1);                           \
                }                                                                 \
                float l0, h0, l1, h1;                                             \
                unpack2(a0, l0, h0);                                              \
                unpack2(a1, l1, h1);                                              \
                part[kh][gate][b][jloc] = (l0 + h0) + (l1 + h1);                  \
            }                                                                     \
        } while (0)

        if (kh == rank) {
            DO_DOT();                               // local half: no peer dependency
            mbar_wait_cluster(mloc, s & 1);         // then align with peer phase
        } else {
            mbar_wait_cluster(mloc, s & 1);         // peer h for step s
            DO_DOT();
        }
        __syncthreads();                            // partials visible

        if (tid < 256) {
            float gi = part[0][0][ub][uj] + part[1][0][ub][uj] + xgi + bi;
            float gf = part[0][1][ub][uj] + part[1][1][ub][uj] + xgf + bfo;
            float gg = part[0][2][ub][uj] + part[1][2][ub][uj] + xgg + bg;
            float go = part[0][3][ub][uj] + part[1][3][ub][uj] + xgo + bo;
            c_reg = sigmoid_a(gf) * c_reg + sigmoid_a(gi) * tanh_a(gg);
            float hv = sigmoid_a(go) * tanh_a(c_reg);
            h_s[p ^ 1][ub][hidx] = hv;
            asm volatile("st.shared::cluster.f32 [%0], %1;"
                         :: "r"(hrem[p ^ 1]), "f"(hv) : "memory");
            if (s == SEQ - 1) g_hlast[(bbase + ub) * NH + hidx] = hv;
        }
        __syncthreads();                            // drains STS (incl. DSMEM) before arrive
        if (tid == 0) mbar_arrive_remote(mrem);     // single release-arrive
        p ^= 1;
    }
    cluster_sync_inline();   // keep both CTAs alive for in-flight DSMEM traffic
}

// ================= Phase 3: logits = h_last @ Wd + bd =================
__global__ void final_dense(const float* __restrict__ Wd, const float* __restrict__ bd,
                            float* __restrict__ out)
{
    int b = threadIdx.x;   // 256 threads, 1 block
    float a0 = bd[0], a1 = bd[1];
    const float* hp = g_hlast + b * NH;
    #pragma unroll 8
    for (int k = 0; k < NH; k++) {
        float h = hp[k];
        a0 += h * Wd[k * 2 + 0];
        a1 += h * Wd[k * 2 + 1];
    }
    out[b * 2 + 0] = a0;
    out[b * 2 + 1] = a1;
}

// ================= launch =================
extern "C" void kernel_launch(void* const* d_in, const int* in_sizes, int n_in,
                              void* d_out, int out_size)
{
    const float* x  = (const float*)d_in[0];
    const float* Wi = (const float*)d_in[1];
    const float* Wh = (const float*)d_in[2];
    const float* b  = (const float*)d_in[3];
    const float* Wd = (const float*)d_in[4];
    const float* bd = (const float*)d_in[5];
    float* out = (float*)d_out;

    cudaFuncSetAttribute(gemm_xw, cudaFuncAttributeMaxDynamicSharedMemorySize, SMEM_G);

    dim3 g1((BATCH * SEQ) / BM, G4 / BN);   // 1024 x 4
    gemm_xw<<<g1, 256, SMEM_G>>>(x, Wi);
    lstm_rec<<<128, 512>>>(Wh, b);          // 64 clusters of 2 CTAs
    final_dense<<<1, 256>>>(Wd, bd, out);
}

// round 17
// speedup vs baseline: 1.4504x; 1.4476x over previous
#include <cuda_runtime.h>
#include <cuda_fp16.h>
#include <mma.h>
#include <cstdint>

using namespace nvcuda;

#define BATCH 256
#define SEQ   512
#define NIN   512
#define NH    128
#define G4    512   // 4*NH
#define MTOT  (BATCH * SEQ)

// -------- scratch (static device globals; no runtime allocation) --------
__device__ float g_xg[(size_t)SEQ * BATCH * G4];   // x_gates[s][b][col]
__device__ float g_hlast[BATCH * NH];

// ---------------- helpers ----------------
__device__ __forceinline__ uint64_t ffma2(uint64_t a, uint64_t b, uint64_t c) {
    uint64_t d;
    asm("fma.rn.f32x2 %0, %1, %2, %3;" : "=l"(d) : "l"(a), "l"(b), "l"(c));
    return d;
}
__device__ __forceinline__ uint64_t pack2(float lo, float hi) {
    uint64_t d; asm("mov.b64 %0, {%1, %2};" : "=l"(d) : "f"(lo), "f"(hi)); return d;
}
__device__ __forceinline__ void unpack2(uint64_t v, float& lo, float& hi) {
    asm("mov.b64 {%0, %1}, %2;" : "=f"(lo), "=f"(hi) : "l"(v));
}
__device__ __forceinline__ void cluster_sync_inline() {
    asm volatile("barrier.cluster.arrive.aligned;" ::: "memory");
    asm volatile("barrier.cluster.wait.aligned;" ::: "memory");
}
__device__ __forceinline__ float tanh_a(float x) {
    float r; asm("tanh.approx.f32 %0, %1;" : "=f"(r) : "f"(x)); return r;
}
__device__ __forceinline__ float sigmoid_a(float x) {
    return fmaf(tanh_a(0.5f * x), 0.5f, 0.5f);
}
__device__ __forceinline__ void cp_async16(void* smem, const void* g) {
    uint32_t s = (uint32_t)__cvta_generic_to_shared(smem);
    asm volatile("cp.async.cg.shared.global [%0], [%1], 16;" :: "r"(s), "l"(g));
}
__device__ __forceinline__ void mbar_init(uint32_t addr, uint32_t cnt) {
    asm volatile("mbarrier.init.shared.b64 [%0], %1;" :: "r"(addr), "r"(cnt) : "memory");
}
__device__ __forceinline__ void mbar_arrive_remote(uint32_t raddr) {
    asm volatile("mbarrier.arrive.release.cluster.shared::cluster.b64 _, [%0];"
                 :: "r"(raddr) : "memory");
}
__device__ __forceinline__ void mbar_wait_cluster(uint32_t addr, uint32_t parity) {
    uint32_t done;
    do {
        asm volatile(
            "{\n\t.reg .pred p;\n\t"
            "mbarrier.try_wait.parity.acquire.cluster.shared::cta.b64 p, [%1], %2, 0x989680;\n\t"
            "selp.b32 %0, 1, 0, p;\n\t}"
            : "=r"(done) : "r"(addr), "r"(parity) : "memory");
    } while (!done);
}

// ================= Phase 1: x_gates = x @ Wi (fp16 wmma, in-kernel conversion) =================
// cp.async 2-stage fp32 staging (R6-proven) -> per-kt fp32->fp16 smem convert ->
// HMMA.16816 (halved mma instruction stream vs tf32).
#define BM 128
#define BN 128
#define BK 32
#define LDA32 40     // floats
#define LDB32 136    // floats
#define LDA_H 40     // halves
#define LDB_H 136    // halves
// byte offsets in dynamic smem
#define OFF32A 0                         // 2*128*40*4 = 40960
#define OFF32B 40960                     // 2*32*136*4 = 34816
#define OFF16A 75776                     // 128*40*2   = 10240
#define OFF16B 86016                     // 32*136*2   = 8704
#define SMEM_GH 94720

__global__ void __launch_bounds__(256, 2) gemm_xw_h(const float* __restrict__ X,
                                                    const float* __restrict__ Wi)
{
    extern __shared__ __align__(16) char gsm[];
    float (*As32)[BM][LDA32] = (float (*)[BM][LDA32])(gsm + OFF32A);
    float (*Bs32)[BK][LDB32] = (float (*)[BK][LDB32])(gsm + OFF32B);
    __half (*As16)[LDA_H]    = (__half (*)[LDA_H])(gsm + OFF16A);
    __half (*Bs16)[LDB_H]    = (__half (*)[LDB_H])(gsm + OFF16B);

    const int m0 = blockIdx.x * BM;
    const int n0 = blockIdx.y * BN;
    const int tid = threadIdx.x;
    const int warp = tid >> 5;
    const int wm = warp >> 2;     // 0..1 : 64-row slab
    const int wn = warp & 3;      // 0..3 : 32-col slab

    wmma::fragment<wmma::accumulator, 16, 16, 16, float> c[4][2];
    #pragma unroll
    for (int i = 0; i < 4; i++)
        #pragma unroll
        for (int j = 0; j < 2; j++)
            wmma::fill_fragment(c[i][j], 0.0f);

    auto load_tiles = [&](int kt, int buf) {
        const int k0 = kt * BK;
        #pragma unroll
        for (int q = 0; q < 4; q++) {
            int e = tid + q * 256;           // 0..1023
            int row = e >> 3;                // 0..127
            int c4 = (e & 7) * 4;            // 0..28
            cp_async16(&As32[buf][row][c4], &X[(size_t)(m0 + row) * NIN + k0 + c4]);
        }
        #pragma unroll
        for (int q = 0; q < 4; q++) {
            int e = tid + q * 256;
            int row = e >> 5;                // 0..31
            int c4 = (e & 31) * 4;           // 0..124
            cp_async16(&Bs32[buf][row][c4], &Wi[(size_t)(k0 + row) * G4 + n0 + c4]);
        }
        asm volatile("cp.async.commit_group;" ::: "memory");
    };

    // convert fp32 stage buf -> fp16 tiles (16 elems/thread for A and B each)
    auto convert = [&](int buf) {
        {   // A: 128 x 32 floats; thread: row = tid>>1, half = tid&1
            const int row = tid >> 1, half = tid & 1;
            const float* src = &As32[buf][row][half * 16];
            uint32_t pk[8];
            #pragma unroll
            for (int u = 0; u < 4; u++) {
                float4 v = ((const float4*)src)[u];
                __half2 h01 = __floats2half2_rn(v.x, v.y);
                __half2 h23 = __floats2half2_rn(v.z, v.w);
                pk[u * 2]     = *(uint32_t*)&h01;
                pk[u * 2 + 1] = *(uint32_t*)&h23;
            }
            uint4* dst = (uint4*)&As16[row][half * 16];
            dst[0] = make_uint4(pk[0], pk[1], pk[2], pk[3]);
            dst[1] = make_uint4(pk[4], pk[5], pk[6], pk[7]);
        }
        {   // B: 32 x 128 floats; thread: row = tid>>3, seg = tid&7
            const int row = tid >> 3, seg = tid & 7;
            const float* src = &Bs32[buf][row][seg * 16];
            uint32_t pk[8];
            #pragma unroll
            for (int u = 0; u < 4; u++) {
                float4 v = ((const float4*)src)[u];
                __half2 h01 = __floats2half2_rn(v.x, v.y);
                __half2 h23 = __floats2half2_rn(v.z, v.w);
                pk[u * 2]     = *(uint32_t*)&h01;
                pk[u * 2 + 1] = *(uint32_t*)&h23;
            }
            uint4* dst = (uint4*)&Bs16[row][seg * 16];
            dst[0] = make_uint4(pk[0], pk[1], pk[2], pk[3]);
            dst[1] = make_uint4(pk[4], pk[5], pk[6], pk[7]);
        }
    };

    load_tiles(0, 0);

    const int NT = NIN / BK;   // 16
    for (int kt = 0; kt < NT; kt++) {
        if (kt + 1 < NT) {
            load_tiles(kt + 1, (kt + 1) & 1);
            asm volatile("cp.async.wait_group 1;" ::: "memory");
        } else {
            asm volatile("cp.async.wait_group 0;" ::: "memory");
        }
        __syncthreads();                 // fp32 stage buf[kt&1] complete

        convert(kt & 1);
        __syncthreads();                 // fp16 tiles ready

        #pragma unroll
        for (int kk = 0; kk < BK; kk += 16) {
            wmma::fragment<wmma::matrix_a, 16, 16, 16, __half, wmma::row_major> af[4];
            wmma::fragment<wmma::matrix_b, 16, 16, 16, __half, wmma::row_major> bf[2];
            #pragma unroll
            for (int i = 0; i < 4; i++)
                wmma::load_matrix_sync(af[i], &As16[wm * 64 + i * 16][kk], LDA_H);
            #pragma unroll
            for (int j = 0; j < 2; j++)
                wmma::load_matrix_sync(bf[j], &Bs16[kk][wn * 32 + j * 16], LDB_H);
            #pragma unroll
            for (int i = 0; i < 4; i++)
                #pragma unroll
                for (int j = 0; j < 2; j++)
                    wmma::mma_sync(c[i][j], af[i], bf[j], c[i][j]);
        }
        __syncthreads();                 // all reads done before next convert overwrites
    }

    // Epilogue: gmem row m = b*SEQ + s -> g_xg row s*BATCH + b. 16-row tiles: constant b.
    #pragma unroll
    for (int i = 0; i < 4; i++) {
        int m = m0 + wm * 64 + i * 16;
        int b = m >> 9;
        int s = m & 511;
        float* base = g_xg + ((size_t)s * BATCH + b) * G4 + n0 + wn * 32;
        #pragma unroll
        for (int j = 0; j < 2; j++)
            wmma::store_matrix_sync(base + j * 16, c[i][j], (size_t)BATCH * G4, wmma::mem_row_major);
    }
}

// ================= Phase 2: LSTM recurrence (R6-proven, frozen) =================
__global__ void __launch_bounds__(512, 1) __cluster_dims__(2, 1, 1)
lstm_rec(const float* __restrict__ Wh, const float* __restrict__ bias)
{
    __shared__ __align__(16) float h_s[2][4][NH];     // double-buffered h
    __shared__ float part[2][4][4][64];               // [kh][gate][b][jloc]
    __shared__ __align__(8) unsigned long long mbar;

    const int tid  = threadIdx.x;
    const int lane = tid & 31;
    const int warp = tid >> 5;
    const int rank  = blockIdx.x & 1;
    const int bbase = (blockIdx.x >> 1) * 4;

    const int kh   = warp >> 3;
    const int w7   = warp & 7;
    const int gate = w7 >> 1;
    const int jloc = (w7 & 1) * 32 + lane;
    const int colg = gate * NH + rank * 64 + jloc;

    uint64_t w[32];
    #pragma unroll
    for (int i = 0; i < 32; i++) {
        int k = kh * 64 + 2 * i;
        w[i] = pack2(Wh[(size_t)k * G4 + colg], Wh[(size_t)(k + 1) * G4 + colg]);
    }

    const int ub = tid >> 6;
    const int uj = tid & 63;
    const int hidx = rank * 64 + uj;
    float bi = 0.f, bfo = 0.f, bg = 0.f, bo = 0.f;
    if (tid < 256) {
        bi  = bias[0 * NH + hidx];
        bfo = bias[1 * NH + hidx];
        bg  = bias[2 * NH + hidx];
        bo  = bias[3 * NH + hidx];
    }
    float c_reg = 0.0f;

    const uint32_t mloc = (uint32_t)__cvta_generic_to_shared(&mbar);
    uint32_t mrem;
    asm("mapa.shared::cluster.u32 %0, %1, %2;" : "=r"(mrem) : "r"(mloc), "r"(rank ^ 1));
    uint32_t hrem[2];
    #pragma unroll
    for (int pp = 0; pp < 2; pp++) {
        uint32_t la = (uint32_t)__cvta_generic_to_shared(&h_s[pp][ub][hidx]);
        asm("mapa.shared::cluster.u32 %0, %1, %2;" : "=r"(hrem[pp]) : "r"(la), "r"(rank ^ 1));
    }

    if (tid == 0) mbar_init(mloc, 1);
    for (int i = tid; i < 4 * NH; i += 512) (&h_s[0][0][0])[i] = 0.0f;
    __syncthreads();
    cluster_sync_inline();              // peer mbar init'd + h zeroed before any traffic
    if (tid == 0) mbar_arrive_remote(mrem);   // phase 0: peer "step -1 output ready"

    int p = 0;
    for (int s = 0; s < SEQ; s++) {
        float xgi = 0.f, xgf = 0.f, xgg = 0.f, xgo = 0.f;
        if (tid < 256) {
            const float* xp = g_xg + ((size_t)s * BATCH + bbase + ub) * G4 + hidx;
            xgi = xp[0];
            xgf = xp[NH];
            xgg = xp[2 * NH];
            xgo = xp[3 * NH];
        }

        #define DO_DOT()                                                          \
        do {                                                                      \
            _Pragma("unroll")                                                     \
            for (int b = 0; b < 4; b++) {                                         \
                const ulonglong2* h2 = (const ulonglong2*)&h_s[p][b][kh * 64];    \
                uint64_t a0 = 0ull, a1 = 0ull;                                    \
                _Pragma("unroll")                                                 \
                for (int i = 0; i < 8; i++) {                                     \
                    ulonglong2 ha = h2[2 * i];                                    \
                    ulonglong2 hb = h2[2 * i + 1];                                \
                    a0 = ffma2(ha.x, w[4 * i + 0], a0);                           \
                    a0 = ffma2(ha.y, w[4 * i + 1], a0);                           \
                    a1 = ffma2(hb.x, w[4 * i + 2], a1);                           \
                    a1 = ffma2(hb.y, w[4 * i + 3], a1);                           \
                }                                                                 \
                float l0, h0, l1, h1;                                             \
                unpack2(a0, l0, h0);                                              \
                unpack2(a1, l1, h1);                                              \
                part[kh][gate][b][jloc] = (l0 + h0) + (l1 + h1);                  \
            }                                                                     \
        } while (0)

        if (kh == rank) {
            DO_DOT();                               // local half: no peer dependency
            mbar_wait_cluster(mloc, s & 1);         // then align with peer phase
        } else {
            mbar_wait_cluster(mloc, s & 1);         // peer h for step s
            DO_DOT();
        }
        __syncthreads();                            // partials visible

        if (tid < 256) {
            float gi = part[0][0][ub][uj] + part[1][0][ub][uj] + xgi + bi;
            float gf = part[0][1][ub][uj] + part[1][1][ub][uj] + xgf + bfo;
            float gg = part[0][2][ub][uj] + part[1][2][ub][uj] + xgg + bg;
            float go = part[0][3][ub][uj] + part[1][3][ub][uj] + xgo + bo;
            c_reg = sigmoid_a(gf) * c_reg + sigmoid_a(gi) * tanh_a(gg);
            float hv = sigmoid_a(go) * tanh_a(c_reg);
            h_s[p ^ 1][ub][hidx] = hv;
            asm volatile("st.shared::cluster.f32 [%0], %1;"
                         :: "r"(hrem[p ^ 1]), "f"(hv) : "memory");
            if (s == SEQ - 1) g_hlast[(bbase + ub) * NH + hidx] = hv;
        }
        __syncthreads();                            // drains STS (incl. DSMEM) before arrive
        if (tid == 0) mbar_arrive_remote(mrem);     // single release-arrive
        p ^= 1;
    }
    cluster_sync_inline();   // keep both CTAs alive for in-flight DSMEM traffic
}

// ================= Phase 3: logits = h_last @ Wd + bd =================
__global__ void final_dense(const float* __restrict__ Wd, const float* __restrict__ bd,
                            float* __restrict__ out)
{
    int b = threadIdx.x;   // 256 threads, 1 block
    float a0 = bd[0], a1 = bd[1];
    const float* hp = g_hlast + b * NH;
    #pragma unroll 8
    for (int k = 0; k < NH; k++) {
        float h = hp[k];
        a0 += h * Wd[k * 2 + 0];
        a1 += h * Wd[k * 2 + 1];
    }
    out[b * 2 + 0] = a0;
    out[b * 2 + 1] = a1;
}

// ================= launch =================
extern "C" void kernel_launch(void* const* d_in, const int* in_sizes, int n_in,
                              void* d_out, int out_size)
{
    const float* x  = (const float*)d_in[0];
    const float* Wi = (const float*)d_in[1];
    const float* Wh = (const float*)d_in[2];
    const float* b  = (const float*)d_in[3];
    const float* Wd = (const float*)d_in[4];
    const float* bd = (const float*)d_in[5];
    float* out = (float*)d_out;

    cudaFuncSetAttribute(gemm_xw_h, cudaFuncAttributeMaxDynamicSharedMemorySize, SMEM_GH);

    dim3 g1((BATCH * SEQ) / BM, G4 / BN);   // 1024 x 4
    gemm_xw_h<<<g1, 256, SMEM_GH>>>(x, Wi);
    lstm_rec<<<128, 512>>>(Wh, b);          // 64 clusters of 2 CTAs
    final_dense<<<1, 256>>>(Wd, bd, out);
}